// round 1
// baseline (speedup 1.0000x reference)
#include <cuda_runtime.h>
#include <math.h>

#define HH 96
#define WW 96
#define CIN 64
#define COUT 64
#define BATCH 4
#define HW (HH*WW)
#define PIX 32
#define SSTRIDE 578   // 576 ck + 2 pad (conflict avoidance)

// scratch (device globals: no allocation allowed)
__device__ float g_mask[BATCH*9*HW];   // sigmoid(mask conv)  ~1.33 MB
__device__ float g_wt[576*64];         // transposed weight  Wt[ck][o]

// ---------------- kernel 0: weight transpose ----------------
__global__ void k_transpose(const float* __restrict__ w) {
    int t = blockIdx.x*256 + threadIdx.x;
    if (t < 64*576) {
        int o = t / 576, ck = t % 576;
        g_wt[ck*64 + o] = w[t];
    }
}

// ---------------- kernel 1: mask conv (9ch 3x3) + sigmoid ----------------
__global__ __launch_bounds__(256) void k_mask(const float* __restrict__ x,
                                              const float* __restrict__ mw,
                                              const float* __restrict__ mb) {
    __shared__ float smw[64*84];   // per-c row of 81 weights, padded to 84
    __shared__ float sbias[9];
    int tid = threadIdx.x;
    for (int i = tid; i < 5184; i += 256) {
        int k = i / 576; int r = i % 576; int c = r / 9; int t = r % 9;
        smw[c*84 + k*9 + t] = mw[i];
    }
    if (tid < 9) sbias[tid] = mb[tid];
    __syncthreads();

    int t = blockIdx.x*256 + tid;          // 0..36863
    int b = t / HW; int r = t % HW; int h = r / WW; int w = r % WW;

    float acc[9];
    #pragma unroll
    for (int k = 0; k < 9; k++) acc[k] = sbias[k];

    const float* xb = x + (size_t)b*CIN*HW;
    for (int c = 0; c < 64; c++) {
        float v[9];
        #pragma unroll
        for (int i = 0; i < 3; i++)
          #pragma unroll
          for (int j = 0; j < 3; j++) {
            int yy = h + i - 1, xx = w + j - 1;
            bool ok = (yy >= 0) && (yy < HH) && (xx >= 0) && (xx < WW);
            v[i*3+j] = ok ? __ldg(xb + c*HW + yy*WW + xx) : 0.f;
          }
        const float4* wr = (const float4*)(smw + c*84);
        #pragma unroll
        for (int m = 0; m < 21; m++) {
            float4 wv = wr[m];
            #pragma unroll
            for (int u = 0; u < 4; u++) {
                int idx = m*4 + u;
                if (idx < 81) {
                    int kk = idx / 9, tt = idx % 9;
                    float wval = (u==0)?wv.x:(u==1)?wv.y:(u==2)?wv.z:wv.w;
                    acc[kk] = fmaf(v[tt], wval, acc[kk]);
                }
            }
        }
    }
    #pragma unroll
    for (int k = 0; k < 9; k++) {
        float m = 1.f/(1.f + expf(-acc[k]));
        g_mask[((b*9 + k)*HH + h)*WW + w] = m;
    }
}

// ---------------- kernel 2: fused sample + modulate + GEMM ----------------
// block: 256 threads, tile of 32 pixels (fixed b,h; w0..w0+31)
// smem: ssam[32][578] columns, swt paired weight tile (64 ck), precompute tables
__global__ __launch_bounds__(256, 2) void k_deform(const float* __restrict__ x,
                                                   const float* __restrict__ offset,
                                                   float* __restrict__ out) {
    extern __shared__ float sm[];
    float* ssam  = sm;                       // 32*578 = 18496 floats
    float* swt   = sm + 18496;               // 4096 floats
    float* sp_wy = sm + 18496 + 4096;        // 288
    float* sp_wx = sp_wy + 288;              // 288
    float* sp_m  = sp_wx + 288;              // 288
    int*   sp_y0 = (int*)(sp_m + 288);       // 288
    int*   sp_x0 = sp_y0 + 288;              // 288

    int tid = threadIdx.x;
    int w0 = blockIdx.x * PIX;
    int h  = blockIdx.y;
    int b  = blockIdx.z;

    // ---- phase 0: per (k,p) bilinear setup ----
    for (int e = tid; e < 288; e += 256) {
        int k = e >> 5, p = e & 31;
        int off_base = ((b*18 + 2*k)*HH + h)*WW + w0 + p;
        float oy = offset[off_base];
        float ox = offset[off_base + HW];     // channel 2k+1
        float m  = g_mask[((b*9 + k)*HH + h)*WW + w0 + p];
        float py = (float)(h - 1 + k/3) + oy;
        float px = (float)(w0 + p - 1 + k%3) + ox;
        float y0f = floorf(py), x0f = floorf(px);
        sp_wy[e] = py - y0f;
        sp_wx[e] = px - x0f;
        sp_m[e]  = m;
        sp_y0[e] = (int)y0f;
        sp_x0[e] = (int)x0f;
    }
    __syncthreads();

    // ---- phase 1: gather 32*576 modulated bilinear samples ----
    const float* xb0 = x + (size_t)b*CIN*HW;
    #pragma unroll 2
    for (int j = 0; j < 72; j++) {
        int s = j*256 + tid;                 // 0..18431
        int c = s / 288;
        int e = s - c*288;
        int k = e >> 5, p = e & 31;
        int y0 = sp_y0[e], x0i = sp_x0[e];
        float wy = sp_wy[e], wx = sp_wx[e], m = sp_m[e];
        const float* xb = xb0 + c*HW;
        float v00=0.f, v01=0.f, v10=0.f, v11=0.f;
        bool ya = (y0  >=  0) & (y0  < HH);
        bool yb = (y0  >= -1) & (y0  < HH-1);
        bool xa = (x0i >=  0) & (x0i < WW);
        bool xc = (x0i >= -1) & (x0i < WW-1);
        int base = y0*WW + x0i;
        if (ya & xa) v00 = __ldg(xb + base);
        if (ya & xc) v01 = __ldg(xb + base + 1);
        if (yb & xa) v10 = __ldg(xb + base + WW);
        if (yb & xc) v11 = __ldg(xb + base + WW + 1);
        float top = v00 + (v01 - v00)*wx;
        float bot = v10 + (v11 - v10)*wx;
        float val = (top + (bot - top)*wy) * m;
        ssam[p*SSTRIDE + c*9 + k] = val;
    }
    __syncthreads();

    // ---- phase 2: GEMM 64x(32pix) x K=576, packed f32x2 over ck pairs ----
    int oo = tid & 7;        // 8 o-groups of 8 outputs
    int p  = tid >> 3;       // pixel 0..31
    unsigned long long acc[8];
    #pragma unroll
    for (int i = 0; i < 8; i++) acc[i] = 0ULL;

    for (int kt = 0; kt < 9; kt++) {
        // stage weight tile, pair-interleaved: swt[(ck/2)*128 + o*2 + (ck&1)]
        #pragma unroll
        for (int l = 0; l < 16; l++) {
            int idx = l*256 + tid;           // 0..4095
            int ck = idx >> 6, o = idx & 63;
            float val = g_wt[(kt*64 + ck)*64 + o];
            swt[(ck >> 1)*128 + o*2 + (ck & 1)] = val;
        }
        __syncthreads();

        const float* srow = ssam + p*SSTRIDE + kt*64;
        #pragma unroll 4
        for (int q = 0; q < 32; q++) {
            unsigned long long s2 = *(const unsigned long long*)(srow + 2*q);
            const ulonglong2* wr = (const ulonglong2*)(swt + q*128 + oo*16);
            #pragma unroll
            for (int i = 0; i < 4; i++) {
                ulonglong2 wv = wr[i];
                asm("fma.rn.f32x2 %0, %1, %2, %0;" : "+l"(acc[2*i])   : "l"(wv.x), "l"(s2));
                asm("fma.rn.f32x2 %0, %1, %2, %0;" : "+l"(acc[2*i+1]) : "l"(wv.y), "l"(s2));
            }
        }
        __syncthreads();
    }

    // ---- epilogue: reduce even/odd partials, store ----
    float* ob = out + (size_t)b*COUT*HW + h*WW + w0 + p;
    #pragma unroll
    for (int i = 0; i < 8; i++) {
        int o = oo*8 + i;
        float2 f = *reinterpret_cast<float2*>(&acc[i]);
        ob[(size_t)o*HW] = f.x + f.y;
    }
}

// ---------------- launch ----------------
extern "C" void kernel_launch(void* const* d_in, const int* in_sizes, int n_in,
                              void* d_out, int out_size) {
    const float* x      = (const float*)d_in[0];
    const float* offset = (const float*)d_in[1];
    const float* weight = (const float*)d_in[2];
    const float* mw     = (const float*)d_in[3];
    const float* mb     = (const float*)d_in[4];
    float* out = (float*)d_out;

    (void)in_sizes; (void)n_in; (void)out_size;

    const int SMEM = (18496 + 4096 + 288*3)*4 + 288*2*4;   // 96128 B
    cudaFuncSetAttribute(k_deform, cudaFuncAttributeMaxDynamicSharedMemorySize, SMEM);

    k_transpose<<<144, 256>>>(weight);
    k_mask<<<144, 256>>>(x, mw, mb);
    dim3 grid(WW/PIX, HH, BATCH);   // (3, 96, 4)
    k_deform<<<grid, 256, SMEM>>>(x, offset, out);
}

// round 2
// speedup vs baseline: 5.1699x; 5.1699x over previous
#include <cuda_runtime.h>
#include <math.h>

#define HH 96
#define WW 96
#define HW 9216
#define BATCH 4

// device scratch (no allocations allowed)
__device__ float g_mask[BATCH*9*HW];        // sigmoid(mask conv)
__device__ float g_wtd[9*64*160];           // [kt][c][og*20 + (o&7)*2 + dup], weights duplicated

// ---------------- kernel 0: weight prep (transpose + duplicate + pad layout) ----------------
__global__ void k_prep(const float* __restrict__ w) {
    int t = blockIdx.x*256 + threadIdx.x;       // 0..36863
    if (t < 9*64*64) {
        int kt = t / 4096, r = t & 4095, c = r >> 6, o = r & 63;
        float v = w[o*576 + c*9 + kt];
        int dst = (kt*64 + c)*160 + (o >> 3)*20 + (o & 7)*2;
        *(float2*)(g_wtd + dst) = make_float2(v, v);
    }
}

// ---------------- kernel 1: mask conv (9ch 3x3) + sigmoid ----------------
__global__ __launch_bounds__(256) void k_mask(const float* __restrict__ x,
                                              const float* __restrict__ mw,
                                              const float* __restrict__ mb) {
    __shared__ float smw[64*84];
    __shared__ float sbias[9];
    int tid = threadIdx.x;
    for (int i = tid; i < 5184; i += 256) {
        int k = i / 576; int r = i % 576; int c = r / 9; int t = r % 9;
        smw[c*84 + k*9 + t] = mw[i];
    }
    if (tid < 9) sbias[tid] = mb[tid];
    __syncthreads();

    int t = blockIdx.x*256 + tid;
    int b = t / HW; int r = t % HW; int h = r / WW; int w = r % WW;

    float acc[9];
    #pragma unroll
    for (int k = 0; k < 9; k++) acc[k] = sbias[k];

    const float* xb = x + (size_t)b*64*HW;
    for (int c = 0; c < 64; c++) {
        float v[9];
        #pragma unroll
        for (int i = 0; i < 3; i++)
          #pragma unroll
          for (int j = 0; j < 3; j++) {
            int yy = h + i - 1, xx = w + j - 1;
            bool ok = (yy >= 0) && (yy < HH) && (xx >= 0) && (xx < WW);
            v[i*3+j] = ok ? __ldg(xb + c*HW + yy*WW + xx) : 0.f;
          }
        const float* wr = smw + c*84;
        #pragma unroll
        for (int k = 0; k < 9; k++)
          #pragma unroll
          for (int tt = 0; tt < 9; tt++)
            acc[k] = fmaf(v[tt], wr[k*9 + tt], acc[k]);
    }
    #pragma unroll
    for (int k = 0; k < 9; k++) {
        float m = 1.f/(1.f + __expf(-acc[k]));
        g_mask[((b*9 + k)*HH + h)*WW + w] = m;
    }
}

// ---------------- kernel 2: fused sample + modulate + register-tiled GEMM ----------------
// block: 128 threads, 128 linear pixels (within one batch), 64 outputs.
// thread tile: 8 outputs x 8 pixels, f32x2 accumulators over pixel pairs.
#define FMA2(a,b,c) asm("fma.rn.f32x2 %0, %1, %2, %0;" : "+l"(a) : "l"(b), "l"(c))

__global__ __launch_bounds__(128, 3) void k_deform(const float* __restrict__ x,
                                                   const float* __restrict__ offset,
                                                   float* __restrict__ out) {
    extern __shared__ float sm[];
    float* ssam = sm;             // 64 x 132  (samples [c][pix])
    float* swtd = sm + 64*132;    // 64 x 160  (dup weights [c][og*20 + i*2 + d])

    int tid  = threadIdx.x;
    int b    = blockIdx.y;
    int pix0 = blockIdx.x * 128;
    int pix  = pix0 + tid;                 // gather pixel for this thread
    int ph   = pix / WW, pw = pix % WW;

    int og = tid & 7;                      // output group (8 outputs)
    int pg = tid >> 3;                     // pixel group (8 pixels)

    const float* xb = x + (size_t)b*64*HW;

    unsigned long long acc[8][4];
    #pragma unroll
    for (int o = 0; o < 8; o++)
        #pragma unroll
        for (int q = 0; q < 4; q++) acc[o][q] = 0ULL;

    for (int kt = 0; kt < 9; kt++) {
        __syncthreads();   // previous GEMM done before overwriting ssam/swtd

        // ---- stage this tap's dup weights: 10240 floats = 2560 float4 ----
        {
            const float4* src = (const float4*)(g_wtd + kt*10240);
            float4* dst = (float4*)swtd;
            #pragma unroll
            for (int i = 0; i < 20; i++) dst[i*128 + tid] = src[i*128 + tid];
        }

        // ---- per-pixel bilinear setup (registers only) ----
        int ky = kt / 3, kx = kt % 3;
        float oy = offset[(size_t)(b*18 + 2*kt    )*HW + pix];
        float ox = offset[(size_t)(b*18 + 2*kt + 1)*HW + pix];
        float m  = g_mask[(size_t)(b*9 + kt)*HW + pix];
        float py  = (float)(ph - 1 + ky) + oy;
        float pxf = (float)(pw - 1 + kx) + ox;
        float y0f = floorf(py), x0f = floorf(pxf);
        int   y0  = (int)y0f,   x0  = (int)x0f;
        float wy = py - y0f, wx = pxf - x0f;
        float w11 = m*wy*wx;
        float w10 = m*wy - w11;
        float w01 = m*wx - w11;
        float w00 = m - m*wy - m*wx + w11;
        bool ya = (y0 >=  0) & (y0 < HH);
        bool yb = (y0 >= -1) & (y0 < HH-1);
        bool xa = (x0 >=  0) & (x0 < WW);
        bool xc = (x0 >= -1) & (x0 < WW-1);
        if (!(ya & xa)) w00 = 0.f;
        if (!(ya & xc)) w01 = 0.f;
        if (!(yb & xa)) w10 = 0.f;
        if (!(yb & xc)) w11 = 0.f;
        int yc0 = min(max(y0,     0), HH-1), yc1 = min(max(y0 + 1, 0), HH-1);
        int xc0 = min(max(x0,     0), WW-1), xc1 = min(max(x0 + 1, 0), WW-1);
        int i00 = yc0*WW + xc0, i01 = yc0*WW + xc1;
        int i10 = yc1*WW + xc0, i11 = yc1*WW + xc1;

        // ---- gather 64 channels for this pixel ----
        {
            const float* xp = xb;
            float* sp = ssam + tid;
            #pragma unroll 4
            for (int c = 0; c < 64; c++) {
                float v = __ldg(xp + i00)*w00 + __ldg(xp + i01)*w01
                        + __ldg(xp + i10)*w10 + __ldg(xp + i11)*w11;
                sp[0] = v;
                sp += 132;
                xp += HW;
            }
        }
        __syncthreads();

        // ---- GEMM accumulate over this tap's 64 channels ----
        #pragma unroll 2
        for (int c = 0; c < 64; c++) {
            const float* wp = swtd + c*160 + og*20;
            ulonglong2 wv01 = *(const ulonglong2*)(wp);
            ulonglong2 wv23 = *(const ulonglong2*)(wp + 4);
            ulonglong2 wv45 = *(const ulonglong2*)(wp + 8);
            ulonglong2 wv67 = *(const ulonglong2*)(wp + 12);
            unsigned long long wreg[8] = {wv01.x, wv01.y, wv23.x, wv23.y,
                                          wv45.x, wv45.y, wv67.x, wv67.y};
            const float* sp = ssam + c*132 + pg*8;
            ulonglong2 sA = *(const ulonglong2*)(sp);
            ulonglong2 sB = *(const ulonglong2*)(sp + 4);
            unsigned long long sreg[4] = {sA.x, sA.y, sB.x, sB.y};
            #pragma unroll
            for (int o = 0; o < 8; o++) {
                FMA2(acc[o][0], wreg[o], sreg[0]);
                FMA2(acc[o][1], wreg[o], sreg[1]);
                FMA2(acc[o][2], wreg[o], sreg[2]);
                FMA2(acc[o][3], wreg[o], sreg[3]);
            }
        }
    }

    // ---- epilogue: direct packed stores (f32x2 = adjacent pixels) ----
    float* ob = out + (size_t)b*64*HW + pix0 + pg*8;
    #pragma unroll
    for (int o = 0; o < 8; o++) {
        float* op = ob + (size_t)(og*8 + o)*HW;
        #pragma unroll
        for (int q = 0; q < 4; q++)
            *(unsigned long long*)(op + q*2) = acc[o][q];
    }
}

// ---------------- launch ----------------
extern "C" void kernel_launch(void* const* d_in, const int* in_sizes, int n_in,
                              void* d_out, int out_size) {
    const float* x      = (const float*)d_in[0];
    const float* offset = (const float*)d_in[1];
    const float* weight = (const float*)d_in[2];
    const float* mw     = (const float*)d_in[3];
    const float* mb     = (const float*)d_in[4];
    float* out = (float*)d_out;
    (void)in_sizes; (void)n_in; (void)out_size;

    const int SMEM = (64*132 + 64*160) * 4;   // 74752 B
    static int inited = 0;
    cudaFuncSetAttribute(k_deform, cudaFuncAttributeMaxDynamicSharedMemorySize, SMEM);
    (void)inited;

    k_prep<<<144, 256>>>(weight);
    k_mask<<<144, 256>>>(x, mw, mb);
    dim3 grid(HW/128, BATCH);                 // (72, 4)
    k_deform<<<grid, 128, SMEM>>>(x, offset, out);
}